// round 7
// baseline (speedup 1.0000x reference)
#include <cuda_runtime.h>
#include <cstdint>

#define NN 50000
#define NE 600000

// ---------------- scratch (device globals; no allocation allowed) ------------
__device__ float w_deg [NN];
__device__ float w_dinv[NN];
__device__ float w_X [(size_t)NN * 128];   // current layer input (post-activation)
__device__ float w_H [(size_t)NN * 128];   // gemm output
__device__ float w_A [(size_t)NN * 128];   // aggregated output
__device__ int   w_src[NE];
__device__ int   w_dst[NE];
__device__ int   w_is64;

// ---------------- edge index dtype normalization ------------------------------
__global__ void eg_detect(const int* __restrict__ raw) {
    __shared__ int nz;
    if (threadIdx.x == 0) nz = 0;
    __syncthreads();
    if (raw[2 * threadIdx.x + 1] != 0) atomicExch(&nz, 1);
    __syncthreads();
    if (threadIdx.x == 0) w_is64 = (nz == 0) ? 1 : 0;
}

__global__ void eg_convert(const void* __restrict__ ei) {
    int e = blockIdx.x * blockDim.x + threadIdx.x;
    if (e >= 2 * NE) return;
    long long v;
    if (w_is64) v = ((const long long*)ei)[e];
    else        v = (long long)((const int*)ei)[e];
    int vi = (int)v;
    if (vi < 0) vi = 0;
    if (vi >= NN) vi = NN - 1;
    if (e < NE) w_src[e] = vi;
    else        w_dst[e - NE] = vi;
}

// ---------------- degree / norm -----------------------------------------------
__global__ void eg_deg_init() {
    int i = blockIdx.x * blockDim.x + threadIdx.x;
    if (i < NN) w_deg[i] = 1.0f;              // self loop contributes 1
}
__global__ void eg_deg_count() {
    int e = blockIdx.x * blockDim.x + threadIdx.x;
    if (e < NE) atomicAdd(&w_deg[w_dst[e]], 1.0f);
}
__global__ void eg_dinv() {
    int i = blockIdx.x * blockDim.x + threadIdx.x;
    if (i < NN) w_dinv[i] = rsqrtf(w_deg[i]);
}

// ---------------- plain GEMM: H[n, dout] = X[n, din] @ W[din, dout] ------------
__global__ void eg_gemm(const float* __restrict__ X,
                        const float* __restrict__ W,
                        float* __restrict__ H,
                        int din, int dout) {
    long long idx = (long long)blockIdx.x * blockDim.x + threadIdx.x;
    if (idx >= (long long)NN * dout) return;
    int node = (int)(idx / dout);
    int col  = (int)(idx % dout);
    const float* xr = X + (size_t)node * din;
    float acc = 0.0f;
    for (int k = 0; k < din; k++)
        acc += xr[k] * W[(size_t)k * dout + col];
    H[idx] = acc;
}

// ---------------- self-loop term: A = dinv^2 * H --------------------------------
__global__ void eg_self(const float* __restrict__ H,
                        float* __restrict__ A, int dout) {
    long long idx = (long long)blockIdx.x * blockDim.x + threadIdx.x;
    if (idx >= (long long)NN * dout) return;
    int node = (int)(idx / dout);
    float di = w_dinv[node];
    A[idx] = di * di * H[idx];
}

// ---------------- edge scatter: A[dst] += dinv[s] dinv[d] * H[src] --------------
__global__ void eg_scatter(const float* __restrict__ H,
                           float* __restrict__ A, int dout) {
    long long gid = (long long)blockIdx.x * blockDim.x + threadIdx.x;
    if (gid >= (long long)NE * dout) return;
    int e = (int)(gid / dout);
    int c = (int)(gid % dout);
    int s = w_src[e];
    int d = w_dst[e];
    float wgt = w_dinv[s] * w_dinv[d];
    atomicAdd(&A[(size_t)d * dout + c], wgt * H[(size_t)s * dout + c]);
}

// ---------------- activation: X = relu(A + b) -----------------------------------
__global__ void eg_act(const float* __restrict__ A,
                       const float* __restrict__ b,
                       float* __restrict__ X, int dout) {
    long long idx = (long long)blockIdx.x * blockDim.x + threadIdx.x;
    if (idx >= (long long)NN * dout) return;
    int c = (int)(idx % dout);
    float v = A[idx] + b[c];
    X[idx] = v > 0.0f ? v : 0.0f;
}

// ---------------- MLP head: X3(32) -> 16 relu -> 1 -> sigmoid -------------------
__global__ void eg_head(const float* __restrict__ X3,
                        const float* __restrict__ Wf1, const float* __restrict__ bf1,
                        const float* __restrict__ Wf2, const float* __restrict__ bf2,
                        float* __restrict__ out) {
    int node = blockIdx.x * blockDim.x + threadIdx.x;
    if (node >= NN) return;
    const float* xr = X3 + (size_t)node * 32;

    float z = bf2[0];
    for (int j = 0; j < 16; j++) {
        float a = bf1[j];
        for (int k = 0; k < 32; k++)
            a += xr[k] * Wf1[k * 16 + j];
        if (a < 0.0f) a = 0.0f;
        z += a * Wf2[j];
    }
    out[node] = 1.0f / (1.0f + expf(-z));
}

// ---------------- launch ---------------------------------------------------------
static inline unsigned gsz(long long n, int t) { return (unsigned)((n + t - 1) / t); }

extern "C" void kernel_launch(void* const* d_in, const int* in_sizes, int n_in,
                              void* d_out, int out_size) {
    const float* x   = (const float*)d_in[0];
    const void*  ei  = d_in[1];
    const float* W1  = (const float*)d_in[2];
    const float* b1  = (const float*)d_in[3];
    const float* W2  = (const float*)d_in[4];
    const float* b2  = (const float*)d_in[5];
    const float* W3  = (const float*)d_in[6];
    const float* b3  = (const float*)d_in[7];
    const float* Wf1 = (const float*)d_in[8];
    const float* bf1 = (const float*)d_in[9];
    const float* Wf2 = (const float*)d_in[10];
    const float* bf2 = (const float*)d_in[11];
    float* out = (float*)d_out;

    const int T = 256;

    eg_detect <<<1, 256>>>((const int*)ei);
    eg_convert<<<gsz(2LL * NE, T), T>>>(ei);

    eg_deg_init <<<gsz(NN, T), T>>>();
    eg_deg_count<<<gsz(NE, T), T>>>();
    eg_dinv     <<<gsz(NN, T), T>>>();

    // ---- layer 1: x(44) -> 128 ----
    eg_gemm   <<<gsz((long long)NN * 128, T), T>>>(x, W1, w_H, 44, 128);
    eg_self   <<<gsz((long long)NN * 128, T), T>>>(w_H, w_A, 128);
    eg_scatter<<<gsz((long long)NE * 128, T), T>>>(w_H, w_A, 128);
    eg_act    <<<gsz((long long)NN * 128, T), T>>>(w_A, b1, w_X, 128);

    // ---- layer 2: 128 -> 64 ----
    eg_gemm   <<<gsz((long long)NN * 64, T), T>>>(w_X, W2, w_H, 128, 64);
    eg_self   <<<gsz((long long)NN * 64, T), T>>>(w_H, w_A, 64);
    eg_scatter<<<gsz((long long)NE * 64, T), T>>>(w_H, w_A, 64);
    eg_act    <<<gsz((long long)NN * 64, T), T>>>(w_A, b2, w_X, 64);

    // ---- layer 3: 64 -> 32 ----
    eg_gemm   <<<gsz((long long)NN * 32, T), T>>>(w_X, W3, w_H, 64, 32);
    eg_self   <<<gsz((long long)NN * 32, T), T>>>(w_H, w_A, 32);
    eg_scatter<<<gsz((long long)NE * 32, T), T>>>(w_H, w_A, 32);
    eg_act    <<<gsz((long long)NN * 32, T), T>>>(w_A, b3, w_X, 32);

    // ---- MLP head ----
    eg_head<<<gsz(NN, T), T>>>(w_X, Wf1, bf1, Wf2, bf2, out);
}